// round 14
// baseline (speedup 1.0000x reference)
#include <cuda_runtime.h>

// KREmbedding: Gaussian-weighted context embedding aggregation.
// context: [B, C] int32, center: [B] int32, W: [V, D] float32 -> out [B, D] float32
// B=8192, C=32, D=512, SIGMA=1.0
//
// Round 14: int8 sketch prepass + exact integer bound (LTS-traffic attack).
//   Plateau diagnosis: ~195MB of L2 service bytes / ~6300 B/cyc == the 17us
//   wall across R8-R13. Cut bytes: prepass quantizes W[:, :192] to int8
//   (clip +-3.96875, x32, rn) into 9.6MB device scratch; bound pass reads
//   192B/row (vs 640B) and accumulates sum((qx-qc)^2) EXACTLY in int via
//   vsubss4+dp4a (max 3.1M < 2^31), 8-lane-group shfl tree (R13 scheme).
//   Proof: clip is a contraction; saturating sub only shrinks; |dhat-dclip|
//   <= 1/32 => S/1024 <= clipT + sqrt(192*clipT)/16 + 0.19. S > 230*1024 =>
//   clipT > 216 => true d2 > 216 > 208 => expf(-d2/2) == 0.0f exactly in the
//   fp32 reference. Survivors (~0.02% + exact collisions) take the unchanged
//   exact-fp32 cold path against W itself.

#define KB_B 8192
#define KB_C 32
#define KB_D 512
#define KB_V 50000
#define NTHREADS 128            // 4 warps = 2 batch rows per block
#define QWORDS 48               // 192 int8 elems = 48 int32 words per row
#define T_Q (230 * 1024)        // integer threshold on sum of (32*d)^2
#define T_INT (220 * 1024)      // slow-path stage-2 fixed-point threshold
#define ROW_BYTES (KB_D * 4)    // 2048; idx*2048 fits in 32 bits

__device__ int g_q8[KB_V * QWORDS];   // 9.6 MB int8 sketch (packed 4/word)

// ---------------- prepass: quantize W[:, 0:192] to int8 ----------------
__global__ void kre_prep(const float* __restrict__ W)
{
    const int w = blockIdx.x * blockDim.x + threadIdx.x;   // global word id
    if (w >= KB_V * QWORDS) return;
    const int row  = w / QWORDS;
    const int word = w - row * QWORDS;
    const float4 v = __ldg(reinterpret_cast<const float4*>(W + (size_t)row * KB_D) + word);

    int q0 = __float2int_rn(fminf(fmaxf(v.x, -3.96875f), 3.96875f) * 32.f);
    int q1 = __float2int_rn(fminf(fmaxf(v.y, -3.96875f), 3.96875f) * 32.f);
    int q2 = __float2int_rn(fminf(fmaxf(v.z, -3.96875f), 3.96875f) * 32.f);
    int q3 = __float2int_rn(fminf(fmaxf(v.w, -3.96875f), 3.96875f) * 32.f);
    g_q8[w] = (q0 & 0xFF) | ((q1 & 0xFF) << 8) | ((q2 & 0xFF) << 16) | ((q3 & 0xFF) << 24);
}

// ---------------- main kernel ----------------
__device__ __forceinline__ float warp_sum(float v) {
#pragma unroll
    for (int off = 16; off; off >>= 1)
        v += __shfl_xor_sync(0xffffffffu, v, off);
    return v;
}

__device__ __forceinline__ float quarter_d2(float4 r, float4 c) {
    float dx = r.x - c.x, dy = r.y - c.y, dz = r.z - c.z, dw = r.w - c.w;
    float d = dx * dx;
    d = fmaf(dy, dy, d);
    d = fmaf(dz, dz, d);
    d = fmaf(dw, dw, d);
    return d;
}

__device__ __forceinline__ int bound_int(float p) {
    return __float2int_rd(fminf(p, 60000.f) * 1024.f);   // floor -> lower bound
}

// Cold path: warp-uniform entry, ~0.02% of rows. Exact full fp32 distance
// against W; 256-element fixed-point REDUX bound prunes first; lazy acc init.
__device__ __noinline__ float slow_path(const float4* __restrict__ rowp,
                                        const float4* __restrict__ cenp,
                                        int lane,
                                        float4* __restrict__ sacc,
                                        int* __restrict__ flag)
{
    const float4 cen0 = __ldg(&cenp[lane]);
    const float4 cen1 = __ldg(&cenp[lane + 32]);
    const float4 r0   = __ldg(&rowp[lane]);
    const float4 r1   = __ldg(&rowp[lane + 32]);
    const float pa  = quarter_d2(r0, cen0) + quarter_d2(r1, cen1);
    const int s2 = __reduce_add_sync(0xffffffffu, bound_int(pa));
    if (s2 > T_INT) return 0.f;                    // provably w == 0.0f

    if (*flag == 0) {                              // lazy init, warp-uniform
#pragma unroll
        for (int i = 0; i < 4; i++)
            sacc[lane + 32 * i] = make_float4(0.f, 0.f, 0.f, 0.f);
        __syncwarp();
        if (lane == 0) *flag = 1;
    }

    const float4 cen2 = __ldg(&cenp[lane + 64]);
    const float4 cen3 = __ldg(&cenp[lane + 96]);
    const float4 r2   = __ldg(&rowp[lane + 64]);
    const float4 r3   = __ldg(&rowp[lane + 96]);
    const float t  = warp_sum(pa);
    const float d2 = t + warp_sum(quarter_d2(r2, cen2) + quarter_d2(r3, cen3));

    const float e = __expf(-0.5f * d2);

    float4 a;
    a = sacc[lane];
    a.x = fmaf(e, r0.x, a.x); a.y = fmaf(e, r0.y, a.y);
    a.z = fmaf(e, r0.z, a.z); a.w = fmaf(e, r0.w, a.w);
    sacc[lane] = a;
    a = sacc[lane + 32];
    a.x = fmaf(e, r1.x, a.x); a.y = fmaf(e, r1.y, a.y);
    a.z = fmaf(e, r1.z, a.z); a.w = fmaf(e, r1.w, a.w);
    sacc[lane + 32] = a;
    a = sacc[lane + 64];
    a.x = fmaf(e, r2.x, a.x); a.y = fmaf(e, r2.y, a.y);
    a.z = fmaf(e, r2.z, a.z); a.w = fmaf(e, r2.w, a.w);
    sacc[lane + 64] = a;
    a = sacc[lane + 96];
    a.x = fmaf(e, r3.x, a.x); a.y = fmaf(e, r3.y, a.y);
    a.z = fmaf(e, r3.z, a.z); a.w = fmaf(e, r3.w, a.w);
    sacc[lane + 96] = a;
    return e;
}

__global__ __launch_bounds__(NTHREADS, 10)
void kre_kernel(const int* __restrict__ context,
                const int* __restrict__ center,
                const float* __restrict__ W,
                float* __restrict__ out)
{
    const int tid  = threadIdx.x;
    const int lane = tid & 31;
    const int wid  = tid >> 5;
    const int b    = blockIdx.x * 2 + (wid >> 1);  // 2 warps per batch row
    const int half = wid & 1;                      // which 16 context rows
    const int fp   = lane & 7;                     // word slot within group
    const int grp  = lane >> 3;                    // group = row-within-quad

    __shared__ float4 s_acc[4][KB_D / 4];          // per-warp slices (8 KB)
    __shared__ float  s_esum[4];
    __shared__ int    s_flag[4];
    float4* sacc = s_acc[wid];
    if (lane == 0) s_flag[wid] = 0;

    const int cen_idx = __ldg(&center[b]);
    const char* Wb   = reinterpret_cast<const char*>(W);
    const float4* cenp = reinterpret_cast<const float4*>(Wb + (unsigned)cen_idx * ROW_BYTES);

    // quantized center words for this lane's pattern (6 x int32 = 24 int8 elems)
    const int* cq = g_q8 + cen_idx * QWORDS;
    int cenq[6];
#pragma unroll
    for (int j = 0; j < 6; j++) cenq[j] = __ldg(&cq[fp + 8 * j]);

    // all 16 indices for this half in lanes 0..15 (replicated in 16..31)
    const int my_idx = __ldg(&context[b * KB_C + half * 16 + (lane & 15)]);

    float esum = 0.f;

    // ---- 4 quads x 4 rows: group-parallel 192-elem integer bound ----
    unsigned m[4];
#pragma unroll
    for (int q = 0; q < 4; q++) {
        const int idx = __shfl_sync(0xffffffffu, my_idx, 4 * q + grp);
        const int* rq = g_q8 + idx * QWORDS;

        int acc = 0;
#pragma unroll
        for (int j = 0; j < 6; j++) {
            const int x = __ldg(&rq[fp + 8 * j]);
            const int d = __vsubss4(x, cenq[j]);   // saturating: only shrinks
            acc = __dp4a(d, d, acc);               // exact int accumulation
        }
        // 3-level int tree within each 8-lane group: 4 rows reduced at once
        acc += __shfl_xor_sync(0xffffffffu, acc, 4);
        acc += __shfl_xor_sync(0xffffffffu, acc, 2);
        acc += __shfl_xor_sync(0xffffffffu, acc, 1);

        m[q] = __ballot_sync(0xffffffffu, acc <= T_Q);   // warp-uniform mask
    }

    if ((m[0] | m[1] | m[2] | m[3]) != 0) {        // rare (~0.3% of warps)
#pragma unroll
        for (int q = 0; q < 4; q++) {
#pragma unroll
            for (int g = 0; g < 4; g++) {
                if ((m[q] >> (8 * g)) & 1u) {
                    const int idx = __shfl_sync(0xffffffffu, my_idx, 4 * q + g);
                    const float4* rowp = reinterpret_cast<const float4*>(
                        Wb + (unsigned)idx * ROW_BYTES);
                    esum += slow_path(rowp, cenp, lane, sacc, &s_flag[wid]);
                }
            }
        }
    }

    if (lane == 0) s_esum[wid] = esum;
    __syncthreads();

    // pair combine: warps {0,1} -> b0, warps {2,3} -> b1; 64 lanes per pair
    const int pair  = tid >> 6;
    const int ptid  = tid & 63;
    const int b_out = blockIdx.x * 2 + pair;
    const int f0 = s_flag[pair * 2];
    const int f1 = s_flag[pair * 2 + 1];

    float4* op = reinterpret_cast<float4*>(out + (size_t)b_out * KB_D);

    if ((f0 | f1) == 0) {
        // common case (~99% of pairs): no survivors -> output exactly 0
        const float4 z = make_float4(0.f, 0.f, 0.f, 0.f);
#pragma unroll
        for (int i = 0; i < 2; i++)
            __stcs(&op[ptid + 64 * i], z);
    } else {
        const float inv = 1.0f / (s_esum[pair * 2] + s_esum[pair * 2 + 1] + 1e-8f);
#pragma unroll
        for (int i = 0; i < 2; i++) {
            const int j = ptid + 64 * i;
            float4 v = make_float4(0.f, 0.f, 0.f, 0.f);
            if (f0) {
                const float4 a0 = s_acc[pair * 2][j];
                v.x += a0.x; v.y += a0.y; v.z += a0.z; v.w += a0.w;
            }
            if (f1) {
                const float4 a1 = s_acc[pair * 2 + 1][j];
                v.x += a1.x; v.y += a1.y; v.z += a1.z; v.w += a1.w;
            }
            v.x *= inv; v.y *= inv; v.z *= inv; v.w *= inv;
            __stcs(&op[j], v);
        }
    }
}

extern "C" void kernel_launch(void* const* d_in, const int* in_sizes, int n_in,
                              void* d_out, int out_size)
{
    const int* context = (const int*)d_in[0];
    const int* center  = (const int*)d_in[1];
    const float* W     = (const float*)d_in[2];
    for (int i = 0; i < n_in; i++) {
        if (in_sizes[i] == KB_B * KB_C)      context = (const int*)d_in[i];
        else if (in_sizes[i] == KB_B)        center  = (const int*)d_in[i];
        else if (in_sizes[i] > KB_B * KB_C)  W       = (const float*)d_in[i];
    }
    float* out = (float*)d_out;

    const int total_words = KB_V * QWORDS;               // 2,400,000
    kre_prep<<<(total_words + 255) / 256, 256>>>(W);     // sequential in stream
    kre_kernel<<<KB_B / 2, NTHREADS>>>(context, center, W, out);
}

// round 15
// speedup vs baseline: 1.1218x; 1.1218x over previous
#include <cuda_runtime.h>

// KREmbedding: Gaussian-weighted context embedding aggregation.
// context: [B, C] int32, center: [B] int32, W: [V, D] float32 -> out [B, D] float32
// B=8192, C=32, D=512, SIGMA=1.0
//
// Round 15: int8 sketch (R14, proven) restructured for wavefront efficiency.
//   Bound proof (unchanged): prepass quantizes W[:, :192] (clip +-3.96875,
//   x32, rn) to int8. Bound accumulates sum((qx-qc)^2) EXACTLY in int via
//   vsubss4+dp4a (<=3.1M). S > 230*1024 => true d2 > 217 > 208 =>
//   expf(-d2/2) == 0.0f exactly in the fp32 reference. Survivors take the
//   exact fp32 cold path against W.
//   NEW main layout: 4-lane groups; each group owns one row; lane loads its
//   3x int4 (48B) of the 192B sketch row -> LDG.128, 8 rows per warp-pass,
//   2-level group tree + 1 ballot per 8 rows. ~3 L1 wavefronts/row (was 6),
//   ~5 instr/row (was ~6.5).
//   NEW prepass: 1 thread per 16 elems: 4x float4 read, 1x int4 write.

#define KB_B 8192
#define KB_C 32
#define KB_D 512
#define KB_V 50000
#define NTHREADS 128            // 4 warps = 2 batch rows per block
#define QWORDS 48               // 192 int8 elems = 48 int32 words per row
#define QVECS  12               // = QWORDS/4, int4 vectors per row
#define T_Q (230 * 1024)
#define T_INT (220 * 1024)
#define ROW_BYTES (KB_D * 4)

__device__ int4 g_q8[KB_V * QVECS];   // 9.6 MB int8 sketch

// ---------------- prepass: quantize W[:, 0:192] to int8 ----------------
__device__ __forceinline__ int quant4(float4 v) {
    int q0 = __float2int_rn(fminf(fmaxf(v.x, -3.96875f), 3.96875f) * 32.f);
    int q1 = __float2int_rn(fminf(fmaxf(v.y, -3.96875f), 3.96875f) * 32.f);
    int q2 = __float2int_rn(fminf(fmaxf(v.z, -3.96875f), 3.96875f) * 32.f);
    int q3 = __float2int_rn(fminf(fmaxf(v.w, -3.96875f), 3.96875f) * 32.f);
    return (q0 & 0xFF) | ((q1 & 0xFF) << 8) | ((q2 & 0xFF) << 16) | ((q3 & 0xFF) << 24);
}

__global__ void kre_prep(const float* __restrict__ W)
{
    const int v = blockIdx.x * blockDim.x + threadIdx.x;   // int4 vector id
    if (v >= KB_V * QVECS) return;
    const int row  = v / QVECS;
    const int part = v - row * QVECS;                      // 0..11
    const float4* src = reinterpret_cast<const float4*>(W + (size_t)row * KB_D) + part * 4;
    int4 q;
    q.x = quant4(__ldg(&src[0]));
    q.y = quant4(__ldg(&src[1]));
    q.z = quant4(__ldg(&src[2]));
    q.w = quant4(__ldg(&src[3]));
    g_q8[v] = q;
}

// ---------------- main kernel ----------------
__device__ __forceinline__ float warp_sum(float v) {
#pragma unroll
    for (int off = 16; off; off >>= 1)
        v += __shfl_xor_sync(0xffffffffu, v, off);
    return v;
}

__device__ __forceinline__ float quarter_d2(float4 r, float4 c) {
    float dx = r.x - c.x, dy = r.y - c.y, dz = r.z - c.z, dw = r.w - c.w;
    float d = dx * dx;
    d = fmaf(dy, dy, d);
    d = fmaf(dz, dz, d);
    d = fmaf(dw, dw, d);
    return d;
}

__device__ __forceinline__ int bound_int(float p) {
    return __float2int_rd(fminf(p, 60000.f) * 1024.f);
}

__device__ __forceinline__ int dp4_diff(int4 x, int4 c, int acc) {
    int d;
    d = __vsubss4(x.x, c.x); acc = __dp4a(d, d, acc);
    d = __vsubss4(x.y, c.y); acc = __dp4a(d, d, acc);
    d = __vsubss4(x.z, c.z); acc = __dp4a(d, d, acc);
    d = __vsubss4(x.w, c.w); acc = __dp4a(d, d, acc);
    return acc;
}

// Cold path: warp-uniform entry, ~0.02% of rows. Exact full fp32 distance
// against W; fixed-point REDUX bound prunes first; lazy acc init.
__device__ __noinline__ float slow_path(const float4* __restrict__ rowp,
                                        const float4* __restrict__ cenp,
                                        int lane,
                                        float4* __restrict__ sacc,
                                        int* __restrict__ flag)
{
    const float4 cen0 = __ldg(&cenp[lane]);
    const float4 cen1 = __ldg(&cenp[lane + 32]);
    const float4 r0   = __ldg(&rowp[lane]);
    const float4 r1   = __ldg(&rowp[lane + 32]);
    const float pa  = quarter_d2(r0, cen0) + quarter_d2(r1, cen1);
    const int s2 = __reduce_add_sync(0xffffffffu, bound_int(pa));
    if (s2 > T_INT) return 0.f;                    // provably w == 0.0f

    if (*flag == 0) {                              // lazy init, warp-uniform
#pragma unroll
        for (int i = 0; i < 4; i++)
            sacc[lane + 32 * i] = make_float4(0.f, 0.f, 0.f, 0.f);
        __syncwarp();
        if (lane == 0) *flag = 1;
    }

    const float4 cen2 = __ldg(&cenp[lane + 64]);
    const float4 cen3 = __ldg(&cenp[lane + 96]);
    const float4 r2   = __ldg(&rowp[lane + 64]);
    const float4 r3   = __ldg(&rowp[lane + 96]);
    const float t  = warp_sum(pa);
    const float d2 = t + warp_sum(quarter_d2(r2, cen2) + quarter_d2(r3, cen3));

    const float e = __expf(-0.5f * d2);

    float4 a;
    a = sacc[lane];
    a.x = fmaf(e, r0.x, a.x); a.y = fmaf(e, r0.y, a.y);
    a.z = fmaf(e, r0.z, a.z); a.w = fmaf(e, r0.w, a.w);
    sacc[lane] = a;
    a = sacc[lane + 32];
    a.x = fmaf(e, r1.x, a.x); a.y = fmaf(e, r1.y, a.y);
    a.z = fmaf(e, r1.z, a.z); a.w = fmaf(e, r1.w, a.w);
    sacc[lane + 32] = a;
    a = sacc[lane + 64];
    a.x = fmaf(e, r2.x, a.x); a.y = fmaf(e, r2.y, a.y);
    a.z = fmaf(e, r2.z, a.z); a.w = fmaf(e, r2.w, a.w);
    sacc[lane + 64] = a;
    a = sacc[lane + 96];
    a.x = fmaf(e, r3.x, a.x); a.y = fmaf(e, r3.y, a.y);
    a.z = fmaf(e, r3.z, a.z); a.w = fmaf(e, r3.w, a.w);
    sacc[lane + 96] = a;
    return e;
}

__global__ __launch_bounds__(NTHREADS, 10)
void kre_kernel(const int* __restrict__ context,
                const int* __restrict__ center,
                const float* __restrict__ W,
                float* __restrict__ out)
{
    const int tid  = threadIdx.x;
    const int lane = tid & 31;
    const int wid  = tid >> 5;
    const int b    = blockIdx.x * 2 + (wid >> 1);  // 2 warps per batch row
    const int half = wid & 1;                      // which 16 context rows
    const int sub  = lane & 3;                     // int4 slot within group
    const int grp  = lane >> 2;                    // 8 groups of 4 lanes

    __shared__ float4 s_acc[4][KB_D / 4];          // per-warp slices (8 KB)
    __shared__ float  s_esum[4];
    __shared__ int    s_flag[4];
    float4* sacc = s_acc[wid];
    if (lane == 0) s_flag[wid] = 0;

    const int cen_idx = __ldg(&center[b]);
    const char* Wb = reinterpret_cast<const char*>(W);
    const float4* cenp = reinterpret_cast<const float4*>(Wb + (unsigned)cen_idx * ROW_BYTES);

    // quantized center: lane's 3 int4 (48B slice of the 192B row)
    const int4* cq = g_q8 + cen_idx * QVECS;
    int4 cenq[3];
#pragma unroll
    for (int k = 0; k < 3; k++) cenq[k] = __ldg(&cq[sub + 4 * k]);

    // 16 indices for this half, lanes 0..15 (replicated in 16..31)
    const int my_idx = __ldg(&context[b * KB_C + half * 16 + (lane & 15)]);

    float esum = 0.f;

    // ---- 2 passes x 8 rows: 4-lane-group 192-elem integer bound ----
    unsigned m[2];
#pragma unroll
    for (int p = 0; p < 2; p++) {
        const int idx = __shfl_sync(0xffffffffu, my_idx, 8 * p + grp);
        const int4* rq = g_q8 + idx * QVECS;

        int acc = 0;
#pragma unroll
        for (int k = 0; k < 3; k++)
            acc = dp4_diff(__ldg(&rq[sub + 4 * k]), cenq[k], acc);

        // 2-level tree within each 4-lane group: 8 rows reduced at once
        acc += __shfl_xor_sync(0xffffffffu, acc, 2);
        acc += __shfl_xor_sync(0xffffffffu, acc, 1);

        m[p] = __ballot_sync(0xffffffffu, acc <= T_Q);   // warp-uniform mask
    }

    if ((m[0] | m[1]) != 0) {                      // rare (~0.1% of warps)
#pragma unroll
        for (int p = 0; p < 2; p++) {
#pragma unroll
            for (int g = 0; g < 8; g++) {
                if ((m[p] >> (4 * g)) & 1u) {
                    const int idx = __shfl_sync(0xffffffffu, my_idx, 8 * p + g);
                    const float4* rowp = reinterpret_cast<const float4*>(
                        Wb + (unsigned)idx * ROW_BYTES);
                    esum += slow_path(rowp, cenp, lane, sacc, &s_flag[wid]);
                }
            }
        }
    }

    if (lane == 0) s_esum[wid] = esum;
    __syncthreads();

    // pair combine: warps {0,1} -> b0, warps {2,3} -> b1; 64 lanes per pair
    const int pair  = tid >> 6;
    const int ptid  = tid & 63;
    const int b_out = blockIdx.x * 2 + pair;
    const int f0 = s_flag[pair * 2];
    const int f1 = s_flag[pair * 2 + 1];

    float4* op = reinterpret_cast<float4*>(out + (size_t)b_out * KB_D);

    if ((f0 | f1) == 0) {
        const float4 z = make_float4(0.f, 0.f, 0.f, 0.f);
#pragma unroll
        for (int i = 0; i < 2; i++)
            __stcs(&op[ptid + 64 * i], z);
    } else {
        const float inv = 1.0f / (s_esum[pair * 2] + s_esum[pair * 2 + 1] + 1e-8f);
#pragma unroll
        for (int i = 0; i < 2; i++) {
            const int j = ptid + 64 * i;
            float4 v = make_float4(0.f, 0.f, 0.f, 0.f);
            if (f0) {
                const float4 a0 = s_acc[pair * 2][j];
                v.x += a0.x; v.y += a0.y; v.z += a0.z; v.w += a0.w;
            }
            if (f1) {
                const float4 a1 = s_acc[pair * 2 + 1][j];
                v.x += a1.x; v.y += a1.y; v.z += a1.z; v.w += a1.w;
            }
            v.x *= inv; v.y *= inv; v.z *= inv; v.w *= inv;
            __stcs(&op[j], v);
        }
    }
}

extern "C" void kernel_launch(void* const* d_in, const int* in_sizes, int n_in,
                              void* d_out, int out_size)
{
    const int* context = (const int*)d_in[0];
    const int* center  = (const int*)d_in[1];
    const float* W     = (const float*)d_in[2];
    for (int i = 0; i < n_in; i++) {
        if (in_sizes[i] == KB_B * KB_C)      context = (const int*)d_in[i];
        else if (in_sizes[i] == KB_B)        center  = (const int*)d_in[i];
        else if (in_sizes[i] > KB_B * KB_C)  W       = (const float*)d_in[i];
    }
    float* out = (float*)d_out;

    const int total_vecs = KB_V * QVECS;                 // 600,000
    kre_prep<<<(total_vecs + 255) / 256, 256>>>(W);
    kre_kernel<<<KB_B / 2, NTHREADS>>>(context, center, W, out);
}